// round 11
// baseline (speedup 1.0000x reference)
#include <cuda_runtime.h>
#include <cstdint>

#define B_DIM 4096
#define F_DIM 16384
#define G_DIM 512
#define S_DIM 32
#define N_IDX (G_DIM * S_DIM)   // 16384 == F_DIM: idx is a permutation of features

#define ROWS_PER_CTA 4          // one warp per row
#define THREADS 128

// Folded per-feature weight pw[f] = w_group[j]*fc_kernel[j/S] where idx[j]==f.
// group_idx is a permutation of [0, F): every slot overwritten each launch,
// so no zeroing and no atomics needed.
__device__ float g_pw[F_DIM];

// Scatter with in-kernel dtype detection (JAX may hand int32 despite int64 in
// the reference: little-endian int64 < 2^31 has every odd 32-bit word == 0).
__global__ void scatter_weights_kernel(const unsigned int* __restrict__ idx_words,
                                       const float* __restrict__ w_group,
                                       const float* __restrict__ fc_kernel) {
    __shared__ int s_is64;
    if (threadIdx.x == 0) {
        int is64 = 1;
        #pragma unroll
        for (int j = 0; j < 32; j++) {
            if (idx_words[2 * j + 1] != 0u) { is64 = 0; break; }
        }
        s_is64 = is64;
    }
    __syncthreads();

    int j = blockIdx.x * blockDim.x + threadIdx.x;  // j in [0, N_IDX)
    if (j < N_IDX) {
        int g = j / S_DIM;
        float w = w_group[j] * fc_kernel[g];  // UNITS == 1
        long long f;
        if (s_is64) {
            f = ((const long long*)idx_words)[j];
        } else {
            f = (long long)((const int*)idx_words)[j];
        }
        if (f >= 0 && f < F_DIM) {
            g_pw[(int)f] = w;   // permutation: exactly one writer per slot
        }
    }
}

// One WARP per row. The 4 warps of a CTA stream different rows but share the
// same pw positions in near-lockstep: warp 0's pw miss fills L1, warps 1-3
// hit L1 -> pw L2 traffic drops 4x, pulling total L2 service (~11.8 TB/s,
// at the LTS cap) down to ~7.4 TB/s so DRAM can climb.
// No __syncthreads: pure shuffle reduction, single x-stream per thread.
__global__ void __launch_bounds__(THREADS, 12) row_dot_warp_kernel(const float* __restrict__ x,
                                                                   float* __restrict__ out) {
    const int warp = threadIdx.x >> 5;
    const int lane = threadIdx.x & 31;
    const int b = blockIdx.x * ROWS_PER_CTA + warp;

    const float4* __restrict__ xr = reinterpret_cast<const float4*>(x + (size_t)b * F_DIM);
    const float4* __restrict__ pw = reinterpret_cast<const float4*>(g_pw);

    float acc = 0.0f;
    // F/4 = 4096 float4; 32 lanes -> 128 iterations per thread
    #pragma unroll 8
    for (int i = lane; i < F_DIM / 4; i += 32) {
        float4 a = __ldcs(&xr[i]);   // streaming: x read exactly once, evict-first
        float4 w = __ldg(&pw[i]);    // L1-cached, shared across the CTA's 4 warps
        acc += a.x * w.x + a.y * w.y + a.z * w.z + a.w * w.w;
    }

    // Warp reduce
    #pragma unroll
    for (int off = 16; off > 0; off >>= 1)
        acc += __shfl_down_sync(0xFFFFFFFFu, acc, off);

    if (lane == 0) out[b] = acc;
}

extern "C" void kernel_launch(void* const* d_in, const int* in_sizes, int n_in,
                              void* d_out, int out_size) {
    const float* x         = (const float*)d_in[0];
    const void*  group_idx = d_in[1];
    const float* w_group   = (const float*)d_in[2];
    const float* fc_kernel = (const float*)d_in[3];
    float* out = (float*)d_out;

    scatter_weights_kernel<<<(N_IDX + 255) / 256, 256>>>(
        (const unsigned int*)group_idx, w_group, fc_kernel);
    row_dot_warp_kernel<<<B_DIM / ROWS_PER_CTA, THREADS>>>(x, out);
}

// round 12
// speedup vs baseline: 1.1862x; 1.1862x over previous
#include <cuda_runtime.h>
#include <cstdint>

#define B_DIM 4096
#define F_DIM 16384
#define G_DIM 512
#define S_DIM 32
#define N_IDX (G_DIM * S_DIM)   // 16384 == F_DIM: idx is a permutation of features

// Folded per-feature weight pw[f] = w_group[j]*fc_kernel[j/S] where idx[j]==f.
// group_idx is a permutation of [0, F): every slot overwritten each launch,
// so no zeroing and no atomics needed.
__device__ float g_pw[F_DIM];

// Scatter with in-kernel dtype detection (JAX may hand int32 despite int64 in
// the reference: little-endian int64 < 2^31 has every odd 32-bit word == 0).
__global__ void scatter_weights_kernel(const unsigned int* __restrict__ idx_words,
                                       const float* __restrict__ w_group,
                                       const float* __restrict__ fc_kernel) {
    __shared__ int s_is64;
    if (threadIdx.x == 0) {
        int is64 = 1;
        #pragma unroll
        for (int j = 0; j < 32; j++) {
            if (idx_words[2 * j + 1] != 0u) { is64 = 0; break; }
        }
        s_is64 = is64;
    }
    __syncthreads();

    int j = blockIdx.x * blockDim.x + threadIdx.x;  // j in [0, N_IDX)
    if (j < N_IDX) {
        int g = j / S_DIM;
        float w = w_group[j] * fc_kernel[g];  // UNITS == 1
        long long f;
        if (s_is64) {
            f = ((const long long*)idx_words)[j];
        } else {
            f = (long long)((const int*)idx_words)[j];
        }
        if (f >= 0 && f < F_DIM) {
            g_pw[(int)f] = w;   // permutation: exactly one writer per slot
        }
    }
}

// One block per row; 4 manually-batched independent load pairs per iteration
// to raise per-thread MLP (R6 profile showed issue=9.7% / DRAM=79%: latency-
// bound, not bandwidth-bound). 4 outer iterations, 8 LDG.128 in flight each.
__global__ void __launch_bounds__(256) row_dot_mlp_kernel(const float* __restrict__ x,
                                                          float* __restrict__ out) {
    const int b = blockIdx.x;
    const int tid = threadIdx.x;

    const float4* __restrict__ xr = reinterpret_cast<const float4*>(x + (size_t)b * F_DIM);
    const float4* __restrict__ pw = reinterpret_cast<const float4*>(g_pw);

    float acc0 = 0.0f, acc1 = 0.0f, acc2 = 0.0f, acc3 = 0.0f;

    // F/4 = 4096 float4 positions; stride 1024 per outer iter, 4 chunks/iter.
    #pragma unroll
    for (int base = 0; base < F_DIM / 4; base += 1024) {
        const int i0 = base + tid;
        // Batch all 8 loads (independent) before any FMA.
        float4 a0 = __ldcs(&xr[i0 +   0]);
        float4 a1 = __ldcs(&xr[i0 + 256]);
        float4 a2 = __ldcs(&xr[i0 + 512]);
        float4 a3 = __ldcs(&xr[i0 + 768]);
        float4 w0 = __ldg(&pw[i0 +   0]);
        float4 w1 = __ldg(&pw[i0 + 256]);
        float4 w2 = __ldg(&pw[i0 + 512]);
        float4 w3 = __ldg(&pw[i0 + 768]);
        acc0 += a0.x * w0.x + a0.y * w0.y + a0.z * w0.z + a0.w * w0.w;
        acc1 += a1.x * w1.x + a1.y * w1.y + a1.z * w1.z + a1.w * w1.w;
        acc2 += a2.x * w2.x + a2.y * w2.y + a2.z * w2.z + a2.w * w2.w;
        acc3 += a3.x * w3.x + a3.y * w3.y + a3.z * w3.z + a3.w * w3.w;
    }
    float acc = (acc0 + acc1) + (acc2 + acc3);

    // Warp reduce
    #pragma unroll
    for (int off = 16; off > 0; off >>= 1)
        acc += __shfl_down_sync(0xFFFFFFFFu, acc, off);

    // Block reduce across 8 warps
    __shared__ float warp_sum[8];
    int wid = tid >> 5, lid = tid & 31;
    if (lid == 0) warp_sum[wid] = acc;
    __syncthreads();
    if (wid == 0) {
        float v = (lid < 8) ? warp_sum[lid] : 0.0f;
        #pragma unroll
        for (int off = 4; off > 0; off >>= 1)
            v += __shfl_down_sync(0xFFFFFFFFu, v, off);
        if (lid == 0) out[b] = v;
    }
}

extern "C" void kernel_launch(void* const* d_in, const int* in_sizes, int n_in,
                              void* d_out, int out_size) {
    const float* x         = (const float*)d_in[0];
    const void*  group_idx = d_in[1];
    const float* w_group   = (const float*)d_in[2];
    const float* fc_kernel = (const float*)d_in[3];
    float* out = (float*)d_out;

    scatter_weights_kernel<<<(N_IDX + 255) / 256, 256>>>(
        (const unsigned int*)group_idx, w_group, fc_kernel);
    row_dot_mlp_kernel<<<B_DIM, 256>>>(x, out);
}